// round 6
// baseline (speedup 1.0000x reference)
#include <cuda_runtime.h>
#include <cstdint>
#include <math_constants.h>

// Farthest point sampling, NPOINT=2.
// Input: xyz [1, B=32, 3, N] float32 (planar per batch: x-plane, y-plane, z-plane).
// Output (float32, [B,2]): idx0 = argmax over y-plane; idx1 = argmax of squared
// distance to point idx0 (first-index tiebreak, matching jnp.argmax).
//
// 2 launches: pass1 (y argmax partials, x4 unrolled, resets ticket), pass2
// (distance argmax partials, x2 unrolled REVERSE sweep for L2 reuse of y,
// x/z evict-first; last block folds final reduction + output write).

#define FPS_B 32
#define BPB   37            // 37*32 = 1184 blocks = one full wave (148 SM x 8 CTA x 256 thr)

__device__ unsigned long long g_part1[FPS_B * BPB];
__device__ unsigned long long g_part2[FPS_B * BPB];
__device__ unsigned int       g_ticket;

// key = (ordered_float(val) << 32) | ~index : max-key == (max val, min index on tie)
static __device__ __forceinline__ unsigned long long make_key(float v, unsigned idx) {
    unsigned u = __float_as_uint(v);
    u = (u & 0x80000000u) ? ~u : (u | 0x80000000u);
    return ((unsigned long long)u << 32) | (unsigned)(~idx);
}

static __device__ __forceinline__ unsigned long long umax64(unsigned long long a,
                                                            unsigned long long b) {
    return a > b ? a : b;
}

// full block max (result valid in thread 0 of warp 0)
static __device__ __forceinline__ unsigned long long block_reduce_max(unsigned long long v) {
    __shared__ unsigned long long s[8];
    int lane = threadIdx.x & 31;
    int wid  = threadIdx.x >> 5;
    #pragma unroll
    for (int o = 16; o; o >>= 1)
        v = umax64(v, __shfl_down_sync(0xffffffffu, v, o));
    if (lane == 0) s[wid] = v;
    __syncthreads();
    if (wid == 0) {
        v = (lane < (int)(blockDim.x >> 5)) ? s[lane] : 0ull;
        #pragma unroll
        for (int o = 16; o; o >>= 1)
            v = umax64(v, __shfl_down_sync(0xffffffffu, v, o));
    }
    return v;
}

// forward order: keeps FIRST index on tie via >
#define UPD_GT(bv, bi, v, i) do { if ((v) > (bv)) { (bv) = (v); (bi) = (i); } } while (0)
// reverse order: later-seen index is smaller -> prefer on tie via >=
#define UPD_GE(bv, bi, v, i) do { if ((v) >= (bv)) { (bv) = (v); (bi) = (i); } } while (0)

#define UPD4_GT(bv, bi, v, base) do { \
    UPD_GT(bv, bi, (v).x, (base) + 0); \
    UPD_GT(bv, bi, (v).y, (base) + 1); \
    UPD_GT(bv, bi, (v).z, (base) + 2); \
    UPD_GT(bv, bi, (v).w, (base) + 3); } while (0)

// Pass 1: per-batch argmax over the y-plane (channel 1). Forward sweep so y is
// L2-resident for pass 2. Unrolled x4 (4 independent LDG.128 in flight).
__global__ void fps_pass1(const float* __restrict__ xyz, int N) {
    if (blockIdx.x == 0 && blockIdx.y == 0 && threadIdx.x == 0) g_ticket = 0;

    const int b = blockIdx.y;
    const float* yp = xyz + (size_t)b * 3 * N + (size_t)N;
    const int N4 = N >> 2;
    const float4* y4 = (const float4*)yp;
    const int S = gridDim.x * blockDim.x;

    float    bv0 = -CUDART_INF_F, bv1 = -CUDART_INF_F,
             bv2 = -CUDART_INF_F, bv3 = -CUDART_INF_F;
    unsigned bi0 = 0u, bi1 = 0u, bi2 = 0u, bi3 = 0u;

    int i = blockIdx.x * blockDim.x + threadIdx.x;
    for (; i + 3 * S < N4; i += 4 * S) {
        float4 a = y4[i];
        float4 c = y4[i + S];
        float4 d = y4[i + 2 * S];
        float4 e = y4[i + 3 * S];
        UPD4_GT(bv0, bi0, a, (unsigned)(i << 2));
        UPD4_GT(bv1, bi1, c, (unsigned)((i + S) << 2));
        UPD4_GT(bv2, bi2, d, (unsigned)((i + 2 * S) << 2));
        UPD4_GT(bv3, bi3, e, (unsigned)((i + 3 * S) << 2));
    }
    for (; i < N4; i += S) {
        float4 a = y4[i];
        UPD4_GT(bv0, bi0, a, (unsigned)(i << 2));
    }
    unsigned long long best = umax64(umax64(make_key(bv0, bi0), make_key(bv1, bi1)),
                                     umax64(make_key(bv2, bi2), make_key(bv3, bi3)));

    if (blockIdx.x == 0) {   // scalar tail (N % 4)
        float bvt = -CUDART_INF_F; unsigned bit_ = 0u;
        for (int t = (N4 << 2) + threadIdx.x; t < N; t += blockDim.x)
            UPD_GT(bvt, bit_, yp[t], (unsigned)t);
        best = umax64(best, make_key(bvt, bit_));
    }

    best = block_reduce_max(best);
    if (threadIdx.x == 0) g_part1[b * BPB + blockIdx.x] = best;
}

// Pass 2: per-batch argmax of min(1e10, ||p - c0||^2), reverse sweep, x2 unrolled
// (6 independent LDG.128 in flight). x,z evict-first; y hot from pass 1.
// Last block to finish performs the global reduction and writes the output.
__global__ void fps_pass2(const float* __restrict__ xyz, int N,
                          float* __restrict__ out) {
    const int b = blockIdx.y;

    // reduce pass-1 partials for this batch -> centroid index
    __shared__ unsigned idx0_sh;
    {
        unsigned long long v = (threadIdx.x < BPB) ? g_part1[b * BPB + threadIdx.x] : 0ull;
        v = block_reduce_max(v);
        if (threadIdx.x == 0) idx0_sh = ~(unsigned)v;
        __syncthreads();
    }
    const unsigned idx0 = idx0_sh;

    const float* xp = xyz + (size_t)b * 3 * N;
    const float* yp = xp + (size_t)N;
    const float* zp = xp + (size_t)2 * N;
    const float cx = __ldg(xp + idx0);
    const float cy = __ldg(yp + idx0);
    const float cz = __ldg(zp + idx0);

    const int N4 = N >> 2;
    const float4* x4 = (const float4*)xp;
    const float4* y4 = (const float4*)yp;
    const float4* z4 = (const float4*)zp;
    const int S = gridDim.x * blockDim.x;

    float    bv0 = -CUDART_INF_F, bv1 = -CUDART_INF_F;
    unsigned bi0 = 0u, bi1 = 0u;

    // scalar tail first (highest indices), forward order -> '>' keeps first;
    // main loop's GE (smaller indices) correctly overrides ties afterwards.
    if (blockIdx.x == 0) {
        for (int t = (N4 << 2) + threadIdx.x; t < N; t += blockDim.x) {
            float dx = xp[t] - cx, dy = yp[t] - cy, dz = zp[t] - cz;
            float d = fminf(dx * dx + dy * dy + dz * dz, 1e10f);
            UPD_GT(bv0, bi0, d, (unsigned)t);
        }
    }

#define DIST_UPD(acc_v, acc_i, vx, vy, vz, base) do { \
    { float dx = (vx).x - cx, dy = (vy).x - cy, dz = (vz).x - cz; \
      float d = fminf(dx * dx + dy * dy + dz * dz, 1e10f); \
      UPD_GE(acc_v, acc_i, d, (base) + 0); } \
    { float dx = (vx).y - cx, dy = (vy).y - cy, dz = (vz).y - cz; \
      float d = fminf(dx * dx + dy * dy + dz * dz, 1e10f); \
      UPD_GE(acc_v, acc_i, d, (base) + 1); } \
    { float dx = (vx).z - cx, dy = (vy).z - cy, dz = (vz).z - cz; \
      float d = fminf(dx * dx + dy * dy + dz * dz, 1e10f); \
      UPD_GE(acc_v, acc_i, d, (base) + 2); } \
    { float dx = (vx).w - cx, dy = (vy).w - cy, dz = (vz).w - cz; \
      float d = fminf(dx * dx + dy * dy + dz * dz, 1e10f); \
      UPD_GE(acc_v, acc_i, d, (base) + 3); } } while (0)

    int j = blockIdx.x * blockDim.x + threadIdx.x;
    for (; j + S < N4; j += 2 * S) {
        int ia = N4 - 1 - j;
        int ib = N4 - 1 - (j + S);
        float4 vxa = __ldcs(x4 + ia);
        float4 vya = y4[ia];
        float4 vza = __ldcs(z4 + ia);
        float4 vxb = __ldcs(x4 + ib);
        float4 vyb = y4[ib];
        float4 vzb = __ldcs(z4 + ib);
        DIST_UPD(bv0, bi0, vxa, vya, vza, (unsigned)(ia << 2));
        DIST_UPD(bv1, bi1, vxb, vyb, vzb, (unsigned)(ib << 2));
    }
    for (; j < N4; j += S) {
        int ia = N4 - 1 - j;
        float4 vxa = __ldcs(x4 + ia);
        float4 vya = y4[ia];
        float4 vza = __ldcs(z4 + ia);
        DIST_UPD(bv0, bi0, vxa, vya, vza, (unsigned)(ia << 2));
    }

    unsigned long long best = umax64(make_key(bv0, bi0), make_key(bv1, bi1));
    best = block_reduce_max(best);
    if (threadIdx.x == 0) g_part2[b * BPB + blockIdx.x] = best;

    // ---- folded finalize: last block reduces all partials, writes output ----
    __shared__ bool s_last;
    __threadfence();
    if (threadIdx.x == 0) {
        unsigned t = atomicAdd(&g_ticket, 1u);
        s_last = (t == gridDim.x * gridDim.y - 1);
    }
    __syncthreads();
    if (s_last) {
        int wid  = threadIdx.x >> 5;
        int lane = threadIdx.x & 31;
        for (int bb = wid; bb < FPS_B; bb += (int)(blockDim.x >> 5)) {
            unsigned long long v1 = 0ull, v2 = 0ull;
            for (int k = lane; k < BPB; k += 32) {
                v1 = umax64(v1, g_part1[bb * BPB + k]);
                v2 = umax64(v2, g_part2[bb * BPB + k]);
            }
            #pragma unroll
            for (int o = 16; o; o >>= 1) {
                v1 = umax64(v1, __shfl_down_sync(0xffffffffu, v1, o));
                v2 = umax64(v2, __shfl_down_sync(0xffffffffu, v2, o));
            }
            if (lane == 0) {
                out[2 * bb + 0] = (float)(~(unsigned)v1);   // exact: idx <= 2^24
                out[2 * bb + 1] = (float)(~(unsigned)v2);
            }
        }
    }
}

extern "C" void kernel_launch(void* const* d_in, const int* in_sizes, int n_in,
                              void* d_out, int out_size) {
    const float* xyz = (const float*)d_in[0];
    const int N = in_sizes[0] / (FPS_B * 3);   // [1, 32, 3, N]
    float* out = (float*)d_out;

    const int THREADS = 256;
    fps_pass1<<<dim3(BPB, FPS_B), THREADS>>>(xyz, N);
    fps_pass2<<<dim3(BPB, FPS_B), THREADS>>>(xyz, N, out);
}

// round 7
// speedup vs baseline: 1.1038x; 1.1038x over previous
#include <cuda_runtime.h>
#include <cstdint>
#include <math_constants.h>

// Farthest point sampling, NPOINT=2 — single fused persistent-wave kernel.
// Input: xyz [1, B=32, 3, N] float32 (planar per batch: x-plane, y-plane, z-plane).
// Output (float32, [B,2]): idx0 = argmax over y-plane; idx1 = argmax of squared
// distance to point idx0 (first-index tiebreak, matching jnp.argmax).
//
// Block k of batch b: pass1 sweep (y argmax, forward, x2 unroll) -> release
// partial -> spin until all 37 blocks of batch b arrived (all 1184 blocks are
// co-resident: launch_bounds(256,8) x 148 SMs = 1184 slots) -> pass2 reverse
// sweep (L2 reuse of y; x/z evict-first) -> ticket; last block reduces all
// partials, writes output, and resets counters for the next graph replay.

#define FPS_B 32
#define BPB   37            // 37*32 = 1184 blocks = one full wave (148 SM x 8 CTA)

__device__ unsigned long long g_part1[FPS_B * BPB];
__device__ unsigned long long g_part2[FPS_B * BPB];
__device__ unsigned int       g_cnt1[FPS_B];   // zero-init; reset by finalize
__device__ unsigned int       g_ticket;        // zero-init; reset by finalize

// key = (ordered_float(val) << 32) | ~index : max-key == (max val, min index on tie)
static __device__ __forceinline__ unsigned long long make_key(float v, unsigned idx) {
    unsigned u = __float_as_uint(v);
    u = (u & 0x80000000u) ? ~u : (u | 0x80000000u);
    return ((unsigned long long)u << 32) | (unsigned)(~idx);
}

static __device__ __forceinline__ unsigned long long umax64(unsigned long long a,
                                                            unsigned long long b) {
    return a > b ? a : b;
}

// full block max (result valid in thread 0 of warp 0)
static __device__ __forceinline__ unsigned long long block_reduce_max(unsigned long long v) {
    __shared__ unsigned long long s[8];
    int lane = threadIdx.x & 31;
    int wid  = threadIdx.x >> 5;
    #pragma unroll
    for (int o = 16; o; o >>= 1)
        v = umax64(v, __shfl_down_sync(0xffffffffu, v, o));
    if (lane == 0) s[wid] = v;
    __syncthreads();
    if (wid == 0) {
        v = (lane < (int)(blockDim.x >> 5)) ? s[lane] : 0ull;
        #pragma unroll
        for (int o = 16; o; o >>= 1)
            v = umax64(v, __shfl_down_sync(0xffffffffu, v, o));
    }
    return v;
}

// forward order: keeps FIRST index on tie via >
#define UPD_GT(bv, bi, v, i) do { if ((v) > (bv)) { (bv) = (v); (bi) = (i); } } while (0)
// reverse order: later-seen index is smaller -> prefer on tie via >=
#define UPD_GE(bv, bi, v, i) do { if ((v) >= (bv)) { (bv) = (v); (bi) = (i); } } while (0)

#define UPD4_GT(bv, bi, v, base) do { \
    UPD_GT(bv, bi, (v).x, (base) + 0); \
    UPD_GT(bv, bi, (v).y, (base) + 1); \
    UPD_GT(bv, bi, (v).z, (base) + 2); \
    UPD_GT(bv, bi, (v).w, (base) + 3); } while (0)

__global__ void __launch_bounds__(256, 8)
fps_fused(const float* __restrict__ xyz, int N, float* __restrict__ out) {
    const int b = blockIdx.x / BPB;        // batch
    const int k = blockIdx.x - b * BPB;    // block-in-batch
    const int S = BPB * blockDim.x;        // per-batch stride (threads covering one plane)

    const float* xp = xyz + (size_t)b * 3 * N;
    const float* yp = xp + (size_t)N;
    const float* zp = xp + (size_t)2 * N;
    const int N4 = N >> 2;
    const float4* x4 = (const float4*)xp;
    const float4* y4 = (const float4*)yp;
    const float4* z4 = (const float4*)zp;

    // ================= Pass 1: y argmax (forward sweep, x2 unroll) =================
    {
        float    bv0 = -CUDART_INF_F, bv1 = -CUDART_INF_F;
        unsigned bi0 = 0u, bi1 = 0u;

        int i = k * blockDim.x + threadIdx.x;
        for (; i + S < N4; i += 2 * S) {
            float4 a = y4[i];
            float4 c = y4[i + S];
            UPD4_GT(bv0, bi0, a, (unsigned)(i << 2));
            UPD4_GT(bv1, bi1, c, (unsigned)((i + S) << 2));
        }
        for (; i < N4; i += S) {
            float4 a = y4[i];
            UPD4_GT(bv0, bi0, a, (unsigned)(i << 2));
        }
        unsigned long long best = umax64(make_key(bv0, bi0), make_key(bv1, bi1));

        if (k == 0) {   // scalar tail (N % 4)
            float bvt = -CUDART_INF_F; unsigned bit_ = 0u;
            for (int t = (N4 << 2) + threadIdx.x; t < N; t += blockDim.x)
                UPD_GT(bvt, bit_, yp[t], (unsigned)t);
            best = umax64(best, make_key(bvt, bit_));
        }

        best = block_reduce_max(best);
        if (threadIdx.x == 0) g_part1[b * BPB + k] = best;
    }

    // ============ per-batch arrival: release partial, spin for 37 arrivals ============
    if (threadIdx.x == 0) {
        __threadfence();                               // release g_part1 write
        unsigned t = atomicAdd(&g_cnt1[b], 1u) + 1u;
        if (t < BPB) {
            volatile unsigned* c = &g_cnt1[b];
            while (*c < BPB) __nanosleep(64);
        }
    }
    __syncthreads();
    __threadfence();                                   // acquire before reading partials

    // reduce pass-1 partials for this batch -> centroid index
    __shared__ unsigned idx0_sh;
    {
        unsigned long long v = (threadIdx.x < BPB) ? g_part1[b * BPB + threadIdx.x] : 0ull;
        v = block_reduce_max(v);
        if (threadIdx.x == 0) idx0_sh = ~(unsigned)v;
        __syncthreads();
    }
    const unsigned idx0 = idx0_sh;
    const float cx = __ldg(xp + idx0);
    const float cy = __ldg(yp + idx0);
    const float cz = __ldg(zp + idx0);

    // ========= Pass 2: distance argmax (reverse sweep; x/z evict-first) =========
    {
        float    bv = -CUDART_INF_F;
        unsigned bi = 0u;

        // scalar tail first (highest indices), forward '>' keeps first; main
        // loop's GE (strictly smaller indices) correctly overrides ties after.
        if (k == 0) {
            for (int t = (N4 << 2) + threadIdx.x; t < N; t += blockDim.x) {
                float dx = xp[t] - cx, dy = yp[t] - cy, dz = zp[t] - cz;
                float d = fminf(dx * dx + dy * dy + dz * dz, 1e10f);
                UPD_GT(bv, bi, d, (unsigned)t);
            }
        }

        for (int j = k * blockDim.x + threadIdx.x; j < N4; j += S) {
            int i = N4 - 1 - j;                // reverse: hot y tail consumed first
            float4 vx = __ldcs(x4 + i);        // streaming, evict-first
            float4 vy = y4[i];                 // hot from pass 1 -> keep cached
            float4 vz = __ldcs(z4 + i);
            unsigned base = (unsigned)(i << 2);
            {
                float dx = vx.x - cx, dy = vy.x - cy, dz = vz.x - cz;
                float d = fminf(dx * dx + dy * dy + dz * dz, 1e10f);
                UPD_GE(bv, bi, d, base + 0);
            }
            {
                float dx = vx.y - cx, dy = vy.y - cy, dz = vz.y - cz;
                float d = fminf(dx * dx + dy * dy + dz * dz, 1e10f);
                UPD_GE(bv, bi, d, base + 1);
            }
            {
                float dx = vx.z - cx, dy = vy.z - cy, dz = vz.z - cz;
                float d = fminf(dx * dx + dy * dy + dz * dz, 1e10f);
                UPD_GE(bv, bi, d, base + 2);
            }
            {
                float dx = vx.w - cx, dy = vy.w - cy, dz = vz.w - cz;
                float d = fminf(dx * dx + dy * dy + dz * dz, 1e10f);
                UPD_GE(bv, bi, d, base + 3);
            }
        }

        unsigned long long best = block_reduce_max(make_key(bv, bi));
        if (threadIdx.x == 0) g_part2[b * BPB + k] = best;
    }

    // ========== folded finalize: last block reduces everything, writes out ==========
    __shared__ bool s_last;
    __threadfence();
    if (threadIdx.x == 0) {
        unsigned t = atomicAdd(&g_ticket, 1u);
        s_last = (t == gridDim.x - 1);
    }
    __syncthreads();
    if (s_last) {
        int wid  = threadIdx.x >> 5;
        int lane = threadIdx.x & 31;
        for (int bb = wid; bb < FPS_B; bb += (int)(blockDim.x >> 5)) {
            unsigned long long v1 = 0ull, v2 = 0ull;
            for (int t = lane; t < BPB; t += 32) {
                v1 = umax64(v1, g_part1[bb * BPB + t]);
                v2 = umax64(v2, g_part2[bb * BPB + t]);
            }
            #pragma unroll
            for (int o = 16; o; o >>= 1) {
                v1 = umax64(v1, __shfl_down_sync(0xffffffffu, v1, o));
                v2 = umax64(v2, __shfl_down_sync(0xffffffffu, v2, o));
            }
            if (lane == 0) {
                out[2 * bb + 0] = (float)(~(unsigned)v1);   // exact: idx <= 2^24
                out[2 * bb + 1] = (float)(~(unsigned)v2);
            }
        }
        __syncthreads();
        // reset counters so the next graph replay starts clean (deterministic)
        if (threadIdx.x == 0) g_ticket = 0;
        if (threadIdx.x < FPS_B) g_cnt1[threadIdx.x] = 0;
    }
}

extern "C" void kernel_launch(void* const* d_in, const int* in_sizes, int n_in,
                              void* d_out, int out_size) {
    const float* xyz = (const float*)d_in[0];
    const int N = in_sizes[0] / (FPS_B * 3);   // [1, 32, 3, N]
    float* out = (float*)d_out;

    fps_fused<<<FPS_B * BPB, 256>>>(xyz, N, out);
}